// round 13
// baseline (speedup 1.0000x reference)
#include <cuda_runtime.h>
#include <cuda_bf16.h>

typedef unsigned long long u64;
typedef unsigned int u32;

// ---------- helpers ----------
__device__ __forceinline__ u64 pk(float a, float b) {
    u64 r; asm("mov.b64 %0, {%1,%2};" : "=l"(r) : "f"(a), "f"(b)); return r;
}
__device__ __forceinline__ u64 fma2(u64 a, u64 b, u64 c) {
    u64 d; asm("fma.rn.f32x2 %0, %1, %2, %3;" : "=l"(d) : "l"(a), "l"(b), "l"(c)); return d;
}
__device__ __forceinline__ float2 upk(u64 a) {
    float x, y; asm("mov.b64 {%0,%1}, %2;" : "=f"(x), "=f"(y) : "l"(a));
    return make_float2(x, y);
}
__device__ __forceinline__ float lrelu(float x) { return fmaxf(x, 0.01f * x); }
__device__ __forceinline__ float softplus_f(float x) {
    return fmaxf(x, 0.0f) + log1pf(expf(-fabsf(x)));
}
// pack two f32 -> bf16x2: low half = first arg, high half = second arg
__device__ __forceinline__ u32 cvt_bf2(float lo_val, float hi_val) {
    u32 r; asm("cvt.rn.bf16x2.f32 %0, %1, %2;" : "=r"(r) : "f"(hi_val), "f"(lo_val));
    return r;
}
__device__ __forceinline__ float bf_lo_f(u32 v) { return __uint_as_float(v << 16); }
__device__ __forceinline__ float bf_hi_f(u32 v) { return __uint_as_float(v & 0xffff0000u); }

__device__ __forceinline__ void mma_k16(float* d, const u32* a, const u32* b) {
    asm volatile(
        "mma.sync.aligned.m16n8k16.row.col.f32.bf16.bf16.f32 "
        "{%0,%1,%2,%3}, {%4,%5,%6,%7}, {%8,%9}, {%0,%1,%2,%3};"
        : "+f"(d[0]), "+f"(d[1]), "+f"(d[2]), "+f"(d[3])
        : "r"(a[0]), "r"(a[1]), "r"(a[2]), "r"(a[3]), "r"(b[0]), "r"(b[1]));
}
__device__ __forceinline__ void mma_k8(float* d, u32 a0, u32 a1, u32 b0) {
    asm volatile(
        "mma.sync.aligned.m16n8k8.row.col.f32.bf16.bf16.f32 "
        "{%0,%1,%2,%3}, {%4,%5}, {%6}, {%0,%1,%2,%3};"
        : "+f"(d[0]), "+f"(d[1]), "+f"(d[2]), "+f"(d[3])
        : "r"(a0), "r"(a1), "r"(b0));
}

#define TPB 128
#define GRIDN 444   // 148 SMs * 3 CTAs

__global__ __launch_bounds__(TPB, 3)
void dln_mma_kernel(const float* __restrict__ xf,
                    const float4* __restrict__ W1, const float* __restrict__ b1,
                    const float* __restrict__ W2f, const float* __restrict__ b2,
                    const float* __restrict__ W_Ld, const float* __restrict__ b_Ld,
                    const float* __restrict__ W_Lo, const float* __restrict__ b_Lo,
                    float4* __restrict__ out, int n, int nwt)
{
    __shared__ u64   sBlo[8 * 4 * 32];   // W2-lo fragments [nt*4+kc][lane]
    __shared__ u64   sB1p[32];           // (b1[2i], b1[2i+1])
    __shared__ u64   sB2p[32];           // (b2[2i], b2[2i+1])
    __shared__ u64   sW3x[32];           // W_Ld row0 pairs
    __shared__ u64   sW3y[32];           // W_Ld row1 pairs
    __shared__ u64   sW3z[32];           // W_Lo pairs
    __shared__ float sB3[3];

    const int tid = threadIdx.x;
    const int wid = tid >> 5;
    const int lane = tid & 31;
    const int g = lane >> 2;     // row-in-8
    const int t = lane & 3;      // col-pair selector

    // ---- stage tables ----
    for (int i = tid; i < 32; i += TPB) {
        sB1p[i] = pk(b1[2 * i], b1[2 * i + 1]);
        sB2p[i] = pk(b2[2 * i], b2[2 * i + 1]);
        sW3x[i] = pk(W_Ld[2 * i],      W_Ld[2 * i + 1]);
        sW3y[i] = pk(W_Ld[64 + 2 * i], W_Ld[64 + 2 * i + 1]);
        sW3z[i] = pk(W_Lo[2 * i],      W_Lo[2 * i + 1]);
    }
    if (tid == 0) { sB3[0] = b_Ld[0]; sB3[1] = b_Ld[1]; sB3[2] = b_Lo[0]; }

    // ---- W2 (layer-2 B): hi in regs, lo in SMEM ----
    // frag (nt,kc): b0={B[k0][n],B[k0+1][n]}, b1={B[k0+8][n],B[k0+9][n]}, n=nt*8+g, k0=kc*16+2t
    u32 bhi[8][4][2];
#pragma unroll
    for (int nt = 0; nt < 8; nt++) {
#pragma unroll
        for (int kc = 0; kc < 4; kc++) {
            const int nn = nt * 8 + g;
            const int k0 = kc * 16 + 2 * t;
            const float f0 = W2f[nn * 64 + k0];
            const float f1 = W2f[nn * 64 + k0 + 1];
            const float f2 = W2f[nn * 64 + k0 + 8];
            const float f3 = W2f[nn * 64 + k0 + 9];
            const u32 h0 = cvt_bf2(f0, f1);
            const u32 h1 = cvt_bf2(f2, f3);
            bhi[nt][kc][0] = h0;
            bhi[nt][kc][1] = h1;
            if (wid == 0) {
                const u32 l0 = cvt_bf2(f0 - bf_lo_f(h0), f1 - bf_hi_f(h0));
                const u32 l1 = cvt_bf2(f2 - bf_lo_f(h1), f3 - bf_hi_f(h1));
                sBlo[(nt * 4 + kc) * 32 + lane] = ((u64)l1 << 32) | (u64)l0;
            }
        }
    }

    // ---- W1 (layer-1 B, k<=4 so one k8 chunk): hi+lo in regs ----
    // b0 = {W1[n][2t], W1[n][2t+1]} for t<2, zero otherwise; n = nt*8+g
    u32 w1hi[8], w1lo[8];
#pragma unroll
    for (int nt = 0; nt < 8; nt++) {
        w1hi[nt] = 0u; w1lo[nt] = 0u;
        if (t < 2) {
            const float4 w = W1[nt * 8 + g];
            const float f0 = (t == 0) ? w.x : w.z;
            const float f1 = (t == 0) ? w.y : w.w;
            const u32 h = cvt_bf2(f0, f1);
            w1hi[nt] = h;
            w1lo[nt] = cvt_bf2(f0 - bf_lo_f(h), f1 - bf_hi_f(h));
        }
    }
    __syncthreads();

    const int TOTW = GRIDN * 4;
    int wt = blockIdx.x * 4 + wid;           // 32-row warp-tile index

    for (; wt < nwt; wt += TOTW) {
#pragma unroll
        for (int mt = 0; mt < 2; mt++) {
            const int r0 = wt * 32 + mt * 16 + g;
            const int r1 = r0 + 8;

            // ---- x fragments (m16k8, k=4 real): hi/lo split ----
            float2 v0 = make_float2(0.f, 0.f), v1 = make_float2(0.f, 0.f);
            if (t < 2) {
                const float2* x2 = (const float2*)xf;
                if (r0 < n) v0 = x2[r0 * 2 + t];
                if (r1 < n) v1 = x2[r1 * 2 + t];
            }
            const u32 a0h = cvt_bf2(v0.x, v0.y);
            const u32 a0l = cvt_bf2(v0.x - bf_lo_f(a0h), v0.y - bf_hi_f(a0h));
            const u32 a1h = cvt_bf2(v1.x, v1.y);
            const u32 a1l = cvt_bf2(v1.x - bf_lo_f(a1h), v1.y - bf_hi_f(a1h));

            // ---- fused per-kc pipeline: layer-1 pair -> split -> layer-2 ----
            float acc[8][4];
#pragma unroll
            for (int nt = 0; nt < 8; nt++) {
                acc[nt][0] = 0.f; acc[nt][1] = 0.f; acc[nt][2] = 0.f; acc[nt][3] = 0.f;
            }
#pragma unroll
            for (int kc = 0; kc < 4; kc++) {
                const int na = 2 * kc, nb = 2 * kc + 1;
                // layer-1 MMA for h1 n-tiles na, nb (3 passes each)
                float la[4] = {0.f, 0.f, 0.f, 0.f};
                float lb[4] = {0.f, 0.f, 0.f, 0.f};
                mma_k8(la, a0h, a1h, w1hi[na]);
                mma_k8(lb, a0h, a1h, w1hi[nb]);
                mma_k8(la, a0h, a1h, w1lo[na]);
                mma_k8(lb, a0h, a1h, w1lo[nb]);
                mma_k8(la, a0l, a1l, w1hi[na]);
                mma_k8(lb, a0l, a1l, w1hi[nb]);

                // bias + lrelu + hi/lo split -> layer-2 A fragments for this kc
                const float2 ba = upk(sB1p[na * 4 + t]);
                const float2 bbv = upk(sB1p[nb * 4 + t]);
                const float ha00 = lrelu(la[0] + ba.x);
                const float ha01 = lrelu(la[1] + ba.y);
                const float ha10 = lrelu(la[2] + ba.x);
                const float ha11 = lrelu(la[3] + ba.y);
                const float hb00 = lrelu(lb[0] + bbv.x);
                const float hb01 = lrelu(lb[1] + bbv.y);
                const float hb10 = lrelu(lb[2] + bbv.x);
                const float hb11 = lrelu(lb[3] + bbv.y);
                u32 ahi4[4], alo4[4];
                ahi4[0] = cvt_bf2(ha00, ha01);
                ahi4[1] = cvt_bf2(ha10, ha11);
                ahi4[2] = cvt_bf2(hb00, hb01);
                ahi4[3] = cvt_bf2(hb10, hb11);
                alo4[0] = cvt_bf2(ha00 - bf_lo_f(ahi4[0]), ha01 - bf_hi_f(ahi4[0]));
                alo4[1] = cvt_bf2(ha10 - bf_lo_f(ahi4[1]), ha11 - bf_hi_f(ahi4[1]));
                alo4[2] = cvt_bf2(hb00 - bf_lo_f(ahi4[2]), hb01 - bf_hi_f(ahi4[2]));
                alo4[3] = cvt_bf2(hb10 - bf_lo_f(ahi4[3]), hb11 - bf_hi_f(ahi4[3]));

                // layer-2 MMA for this k-chunk (3 passes over 8 n-tiles)
                u32 bl[8][2];
#pragma unroll
                for (int nt = 0; nt < 8; nt++) {
                    const u64 v = sBlo[(nt * 4 + kc) * 32 + lane];
                    bl[nt][0] = (u32)v; bl[nt][1] = (u32)(v >> 32);
                }
#pragma unroll
                for (int nt = 0; nt < 8; nt++) mma_k16(acc[nt], ahi4, bhi[nt][kc]);
#pragma unroll
                for (int nt = 0; nt < 8; nt++) mma_k16(acc[nt], ahi4, bl[nt]);
#pragma unroll
                for (int nt = 0; nt < 8; nt++) mma_k16(acc[nt], alo4, bhi[nt][kc]);
            }

            // ---- epilogue: bias + lrelu + head + reduce + softplus + H ----
            u64 D0a = 0ULL, D1a = 0ULL, Oa = 0ULL;
            u64 D0b = 0ULL, D1b = 0ULL, Ob = 0ULL;
#pragma unroll
            for (int nt = 0; nt < 8; nt++) {
                const int i = nt * 4 + t;
                const float2 bb = upk(sB2p[i]);
                const u64 ha = pk(lrelu(acc[nt][0] + bb.x), lrelu(acc[nt][1] + bb.y));
                const u64 hb = pk(lrelu(acc[nt][2] + bb.x), lrelu(acc[nt][3] + bb.y));
                const u64 wx = sW3x[i], wy = sW3y[i], wz = sW3z[i];
                D0a = fma2(wx, ha, D0a); D1a = fma2(wy, ha, D1a); Oa = fma2(wz, ha, Oa);
                D0b = fma2(wx, hb, D0b); D1b = fma2(wy, hb, D1b); Ob = fma2(wz, hb, Ob);
            }
            float v0r, v1r, v2r, v3r, v4r, v5r;
            { const float2 e = upk(D0a); v0r = e.x + e.y; }
            { const float2 e = upk(D1a); v1r = e.x + e.y; }
            { const float2 e = upk(Oa);  v2r = e.x + e.y; }
            { const float2 e = upk(D0b); v3r = e.x + e.y; }
            { const float2 e = upk(D1b); v4r = e.x + e.y; }
            { const float2 e = upk(Ob);  v5r = e.x + e.y; }
            v0r += __shfl_xor_sync(0xffffffffu, v0r, 1); v0r += __shfl_xor_sync(0xffffffffu, v0r, 2);
            v1r += __shfl_xor_sync(0xffffffffu, v1r, 1); v1r += __shfl_xor_sync(0xffffffffu, v1r, 2);
            v2r += __shfl_xor_sync(0xffffffffu, v2r, 1); v2r += __shfl_xor_sync(0xffffffffu, v2r, 2);
            v3r += __shfl_xor_sync(0xffffffffu, v3r, 1); v3r += __shfl_xor_sync(0xffffffffu, v3r, 2);
            v4r += __shfl_xor_sync(0xffffffffu, v4r, 1); v4r += __shfl_xor_sync(0xffffffffu, v4r, 2);
            v5r += __shfl_xor_sync(0xffffffffu, v5r, 1); v5r += __shfl_xor_sync(0xffffffffu, v5r, 2);

            if (t == 0) {
                if (r0 < n) {
                    const float d0 = softplus_f(v0r + sB3[0]);
                    const float d1 = softplus_f(v1r + sB3[1]);
                    const float lo = v2r + sB3[2];
                    const float od = d0 * lo;
                    out[r0] = make_float4(fmaf(d0, d0, 1e-9f), od, od,
                                          fmaf(lo, lo, fmaf(d1, d1, 1e-9f)));
                }
                if (r1 < n) {
                    const float d0 = softplus_f(v3r + sB3[0]);
                    const float d1 = softplus_f(v4r + sB3[1]);
                    const float lo = v5r + sB3[2];
                    const float od = d0 * lo;
                    out[r1] = make_float4(fmaf(d0, d0, 1e-9f), od, od,
                                          fmaf(lo, lo, fmaf(d1, d1, 1e-9f)));
                }
            }
        }
    }
}

extern "C" void kernel_launch(void* const* d_in, const int* in_sizes, int n_in,
                              void* d_out, int out_size)
{
    const float*  x    = (const float*)d_in[0];
    const float4* W1   = (const float4*)d_in[1];
    const float*  b1   = (const float*)d_in[2];
    const float*  W2   = (const float*)d_in[3];
    const float*  b2   = (const float*)d_in[4];
    const float*  W_Ld = (const float*)d_in[5];
    const float*  b_Ld = (const float*)d_in[6];
    const float*  W_Lo = (const float*)d_in[7];
    const float*  b_Lo = (const float*)d_in[8];
    float4* out = (float4*)d_out;

    const int n = in_sizes[0] / 4;                  // rows
    const int nwt = (n + 31) / 32;                  // 32-row warp-tiles
    int grid = (nwt + 3) / 4;
    if (grid > GRIDN) grid = GRIDN;
    dln_mma_kernel<<<grid, TPB>>>(x, W1, b1, W2, b2, W_Ld, b_Ld, W_Lo, b_Lo,
                                  out, n, nwt);
}

// round 14
// speedup vs baseline: 1.0225x; 1.0225x over previous
#include <cuda_runtime.h>
#include <cuda_bf16.h>

typedef unsigned long long u64;
typedef unsigned int u32;

// ---------- helpers ----------
__device__ __forceinline__ u64 pk(float a, float b) {
    u64 r; asm("mov.b64 %0, {%1,%2};" : "=l"(r) : "f"(a), "f"(b)); return r;
}
__device__ __forceinline__ u64 fma2(u64 a, u64 b, u64 c) {
    u64 d; asm("fma.rn.f32x2 %0, %1, %2, %3;" : "=l"(d) : "l"(a), "l"(b), "l"(c)); return d;
}
__device__ __forceinline__ float2 upk(u64 a) {
    float x, y; asm("mov.b64 {%0,%1}, %2;" : "=f"(x), "=f"(y) : "l"(a));
    return make_float2(x, y);
}
__device__ __forceinline__ float lrelu(float x) { return fmaxf(x, 0.01f * x); }
__device__ __forceinline__ float softplus_f(float x) {
    return fmaxf(x, 0.0f) + log1pf(expf(-fabsf(x)));
}
// pack two f32 -> bf16x2: low half = first arg, high half = second arg
__device__ __forceinline__ u32 cvt_bf2(float lo_val, float hi_val) {
    u32 r; asm("cvt.rn.bf16x2.f32 %0, %1, %2;" : "=r"(r) : "f"(hi_val), "f"(lo_val));
    return r;
}
__device__ __forceinline__ float bf_lo_f(u32 v) { return __uint_as_float(v << 16); }
__device__ __forceinline__ float bf_hi_f(u32 v) { return __uint_as_float(v & 0xffff0000u); }

__device__ __forceinline__ void mma_k16(float* d, const u32* a, const u32* b) {
    asm volatile(
        "mma.sync.aligned.m16n8k16.row.col.f32.bf16.bf16.f32 "
        "{%0,%1,%2,%3}, {%4,%5,%6,%7}, {%8,%9}, {%0,%1,%2,%3};"
        : "+f"(d[0]), "+f"(d[1]), "+f"(d[2]), "+f"(d[3])
        : "r"(a[0]), "r"(a[1]), "r"(a[2]), "r"(a[3]), "r"(b[0]), "r"(b[1]));
}
__device__ __forceinline__ void mma_k8(float* d, u32 a0, u32 a1, u32 b0) {
    asm volatile(
        "mma.sync.aligned.m16n8k8.row.col.f32.bf16.bf16.f32 "
        "{%0,%1,%2,%3}, {%4,%5}, {%6}, {%0,%1,%2,%3};"
        : "+f"(d[0]), "+f"(d[1]), "+f"(d[2]), "+f"(d[3])
        : "r"(a0), "r"(a1), "r"(b0));
}

#define TPB 128
#define GRIDN 296   // 148 SMs * 2 CTAs

__global__ __launch_bounds__(TPB, 2)
void dln_mma_kernel(const float* __restrict__ xf,
                    const float4* __restrict__ W1, const float* __restrict__ b1,
                    const float* __restrict__ W2f, const float* __restrict__ b2,
                    const float* __restrict__ W_Ld, const float* __restrict__ b_Ld,
                    const float* __restrict__ W_Lo, const float* __restrict__ b_Lo,
                    float4* __restrict__ out, int n, int nwt)
{
    __shared__ u64   sBlo[8 * 4 * 32];   // W2-lo fragments [nt*4+kc][lane]
    __shared__ u64   sB1p[32];           // (b1[2i], b1[2i+1])
    __shared__ u64   sB2p[32];           // (b2[2i], b2[2i+1])
    __shared__ u64   sW3x[32];           // W_Ld row0 pairs
    __shared__ u64   sW3y[32];           // W_Ld row1 pairs
    __shared__ u64   sW3z[32];           // W_Lo pairs
    __shared__ float sB3[3];

    const int tid = threadIdx.x;
    const int wid = tid >> 5;
    const int lane = tid & 31;
    const int g = lane >> 2;     // row-in-8
    const int t = lane & 3;      // col-pair selector

    // ---- stage tables ----
    for (int i = tid; i < 32; i += TPB) {
        sB1p[i] = pk(b1[2 * i], b1[2 * i + 1]);
        sB2p[i] = pk(b2[2 * i], b2[2 * i + 1]);
        sW3x[i] = pk(W_Ld[2 * i],      W_Ld[2 * i + 1]);
        sW3y[i] = pk(W_Ld[64 + 2 * i], W_Ld[64 + 2 * i + 1]);
        sW3z[i] = pk(W_Lo[2 * i],      W_Lo[2 * i + 1]);
    }
    if (tid == 0) { sB3[0] = b_Ld[0]; sB3[1] = b_Ld[1]; sB3[2] = b_Lo[0]; }

    // ---- W2 (layer-2 B): hi in regs, lo in SMEM ----
    // frag (nt,kc): b0={B[k0][n],B[k0+1][n]}, b1={B[k0+8][n],B[k0+9][n]}, n=nt*8+g, k0=kc*16+2t
    u32 bhi[8][4][2];
#pragma unroll
    for (int nt = 0; nt < 8; nt++) {
#pragma unroll
        for (int kc = 0; kc < 4; kc++) {
            const int nn = nt * 8 + g;
            const int k0 = kc * 16 + 2 * t;
            const float f0 = W2f[nn * 64 + k0];
            const float f1 = W2f[nn * 64 + k0 + 1];
            const float f2 = W2f[nn * 64 + k0 + 8];
            const float f3 = W2f[nn * 64 + k0 + 9];
            const u32 h0 = cvt_bf2(f0, f1);
            const u32 h1 = cvt_bf2(f2, f3);
            bhi[nt][kc][0] = h0;
            bhi[nt][kc][1] = h1;
            if (wid == 0) {
                const u32 l0 = cvt_bf2(f0 - bf_lo_f(h0), f1 - bf_hi_f(h0));
                const u32 l1 = cvt_bf2(f2 - bf_lo_f(h1), f3 - bf_hi_f(h1));
                sBlo[(nt * 4 + kc) * 32 + lane] = ((u64)l1 << 32) | (u64)l0;
            }
        }
    }

    // ---- W1 (layer-1 B, k<=4 so one k8 chunk): hi+lo in regs ----
    // b0 = {W1[n][2t], W1[n][2t+1]} for t<2, zero otherwise; n = nt*8+g
    u32 w1hi[8], w1lo[8];
#pragma unroll
    for (int nt = 0; nt < 8; nt++) {
        w1hi[nt] = 0u; w1lo[nt] = 0u;
        if (t < 2) {
            const float4 w = W1[nt * 8 + g];
            const float f0 = (t == 0) ? w.x : w.z;
            const float f1 = (t == 0) ? w.y : w.w;
            const u32 h = cvt_bf2(f0, f1);
            w1hi[nt] = h;
            w1lo[nt] = cvt_bf2(f0 - bf_lo_f(h), f1 - bf_hi_f(h));
        }
    }
    __syncthreads();

    const int TOTW = GRIDN * 4;
    int wt = blockIdx.x * 4 + wid;           // 32-row warp-tile index
    const float2* x2 = (const float2*)xf;

    // ---- prefetched x fragments for the CURRENT tile: [mt][row-half] ----
    float2 c00 = make_float2(0.f, 0.f), c01 = make_float2(0.f, 0.f);
    float2 c10 = make_float2(0.f, 0.f), c11 = make_float2(0.f, 0.f);
    if (wt < nwt && t < 2) {
        const int ra = wt * 32 + g;
        if (ra < n)      c00 = x2[ra * 2 + t];
        if (ra + 8 < n)  c01 = x2[(ra + 8) * 2 + t];
        if (ra + 16 < n) c10 = x2[(ra + 16) * 2 + t];
        if (ra + 24 < n) c11 = x2[(ra + 24) * 2 + t];
    }

    for (; wt < nwt; wt += TOTW) {
        // ---- issue next tile's x loads immediately (latency hidden by compute) ----
        const int nx = wt + TOTW;
        float2 p00 = make_float2(0.f, 0.f), p01 = make_float2(0.f, 0.f);
        float2 p10 = make_float2(0.f, 0.f), p11 = make_float2(0.f, 0.f);
        if (nx < nwt && t < 2) {
            const int ra = nx * 32 + g;
            if (ra < n)      p00 = x2[ra * 2 + t];
            if (ra + 8 < n)  p01 = x2[(ra + 8) * 2 + t];
            if (ra + 16 < n) p10 = x2[(ra + 16) * 2 + t];
            if (ra + 24 < n) p11 = x2[(ra + 24) * 2 + t];
        }

#pragma unroll
        for (int mt = 0; mt < 2; mt++) {
            const int r0 = wt * 32 + mt * 16 + g;
            const int r1 = r0 + 8;

            // ---- x fragments (m16k8, k=4 real): hi/lo split from prefetched regs ----
            const float2 v0 = (mt == 0) ? c00 : c10;
            const float2 v1 = (mt == 0) ? c01 : c11;
            const u32 a0h = cvt_bf2(v0.x, v0.y);
            const u32 a0l = cvt_bf2(v0.x - bf_lo_f(a0h), v0.y - bf_hi_f(a0h));
            const u32 a1h = cvt_bf2(v1.x, v1.y);
            const u32 a1l = cvt_bf2(v1.x - bf_lo_f(a1h), v1.y - bf_hi_f(a1h));

            // ---- layer-1 MMA: l1 = x @ W1^T (3 passes, 8-wide ILP) ----
            float l1[8][4];
#pragma unroll
            for (int nt = 0; nt < 8; nt++) {
                l1[nt][0] = 0.f; l1[nt][1] = 0.f; l1[nt][2] = 0.f; l1[nt][3] = 0.f;
            }
#pragma unroll
            for (int nt = 0; nt < 8; nt++) mma_k8(l1[nt], a0h, a1h, w1hi[nt]);
#pragma unroll
            for (int nt = 0; nt < 8; nt++) mma_k8(l1[nt], a0h, a1h, w1lo[nt]);
#pragma unroll
            for (int nt = 0; nt < 8; nt++) mma_k8(l1[nt], a0l, a1l, w1hi[nt]);

            // ---- bias + lrelu + hi/lo split -> layer-2 A fragments ----
            u32 ah[8][2], al[8][2];
#pragma unroll
            for (int nt = 0; nt < 8; nt++) {
                const float2 bb = upk(sB1p[nt * 4 + t]);
                const float h00 = lrelu(l1[nt][0] + bb.x);
                const float h01 = lrelu(l1[nt][1] + bb.y);
                const float h10 = lrelu(l1[nt][2] + bb.x);
                const float h11 = lrelu(l1[nt][3] + bb.y);
                const u32 p0 = cvt_bf2(h00, h01);
                const u32 p1 = cvt_bf2(h10, h11);
                ah[nt][0] = p0;
                ah[nt][1] = p1;
                al[nt][0] = cvt_bf2(h00 - bf_lo_f(p0), h01 - bf_hi_f(p0));
                al[nt][1] = cvt_bf2(h10 - bf_lo_f(p1), h11 - bf_hi_f(p1));
            }

            // ---- layer-2 MMA: acc = h1 @ W2^T (3 passes, K=64) ----
            float acc[8][4];
#pragma unroll
            for (int nt = 0; nt < 8; nt++) {
                acc[nt][0] = 0.f; acc[nt][1] = 0.f; acc[nt][2] = 0.f; acc[nt][3] = 0.f;
            }
#pragma unroll
            for (int kc = 0; kc < 4; kc++) {
                u32 ahi4[4] = { ah[2 * kc][0], ah[2 * kc][1], ah[2 * kc + 1][0], ah[2 * kc + 1][1] };
                u32 alo4[4] = { al[2 * kc][0], al[2 * kc][1], al[2 * kc + 1][0], al[2 * kc + 1][1] };
                u32 bl[8][2];
#pragma unroll
                for (int nt = 0; nt < 8; nt++) {
                    const u64 v = sBlo[(nt * 4 + kc) * 32 + lane];
                    bl[nt][0] = (u32)v; bl[nt][1] = (u32)(v >> 32);
                }
#pragma unroll
                for (int nt = 0; nt < 8; nt++) mma_k16(acc[nt], ahi4, bhi[nt][kc]);
#pragma unroll
                for (int nt = 0; nt < 8; nt++) mma_k16(acc[nt], ahi4, bl[nt]);
#pragma unroll
                for (int nt = 0; nt < 8; nt++) mma_k16(acc[nt], alo4, bhi[nt][kc]);
            }

            // ---- epilogue: bias + lrelu + head + reduce + softplus + H ----
            u64 D0a = 0ULL, D1a = 0ULL, Oa = 0ULL;
            u64 D0b = 0ULL, D1b = 0ULL, Ob = 0ULL;
#pragma unroll
            for (int nt = 0; nt < 8; nt++) {
                const int i = nt * 4 + t;
                const float2 bb = upk(sB2p[i]);
                const u64 ha = pk(lrelu(acc[nt][0] + bb.x), lrelu(acc[nt][1] + bb.y));
                const u64 hb = pk(lrelu(acc[nt][2] + bb.x), lrelu(acc[nt][3] + bb.y));
                const u64 wx = sW3x[i], wy = sW3y[i], wz = sW3z[i];
                D0a = fma2(wx, ha, D0a); D1a = fma2(wy, ha, D1a); Oa = fma2(wz, ha, Oa);
                D0b = fma2(wx, hb, D0b); D1b = fma2(wy, hb, D1b); Ob = fma2(wz, hb, Ob);
            }
            float v0r, v1r, v2r, v3r, v4r, v5r;
            { const float2 e = upk(D0a); v0r = e.x + e.y; }
            { const float2 e = upk(D1a); v1r = e.x + e.y; }
            { const float2 e = upk(Oa);  v2r = e.x + e.y; }
            { const float2 e = upk(D0b); v3r = e.x + e.y; }
            { const float2 e = upk(D1b); v4r = e.x + e.y; }
            { const float2 e = upk(Ob);  v5r = e.x + e.y; }
            v0r += __shfl_xor_sync(0xffffffffu, v0r, 1); v0r += __shfl_xor_sync(0xffffffffu, v0r, 2);
            v1r += __shfl_xor_sync(0xffffffffu, v1r, 1); v1r += __shfl_xor_sync(0xffffffffu, v1r, 2);
            v2r += __shfl_xor_sync(0xffffffffu, v2r, 1); v2r += __shfl_xor_sync(0xffffffffu, v2r, 2);
            v3r += __shfl_xor_sync(0xffffffffu, v3r, 1); v3r += __shfl_xor_sync(0xffffffffu, v3r, 2);
            v4r += __shfl_xor_sync(0xffffffffu, v4r, 1); v4r += __shfl_xor_sync(0xffffffffu, v4r, 2);
            v5r += __shfl_xor_sync(0xffffffffu, v5r, 1); v5r += __shfl_xor_sync(0xffffffffu, v5r, 2);

            if (t == 0) {
                if (r0 < n) {
                    const float d0 = softplus_f(v0r + sB3[0]);
                    const float d1 = softplus_f(v1r + sB3[1]);
                    const float lo = v2r + sB3[2];
                    const float od = d0 * lo;
                    out[r0] = make_float4(fmaf(d0, d0, 1e-9f), od, od,
                                          fmaf(lo, lo, fmaf(d1, d1, 1e-9f)));
                }
                if (r1 < n) {
                    const float d0 = softplus_f(v3r + sB3[0]);
                    const float d1 = softplus_f(v4r + sB3[1]);
                    const float lo = v5r + sB3[2];
                    const float od = d0 * lo;
                    out[r1] = make_float4(fmaf(d0, d0, 1e-9f), od, od,
                                          fmaf(lo, lo, fmaf(d1, d1, 1e-9f)));
                }
            }
        }

        // rotate prefetched x into current slot
        c00 = p00; c01 = p01; c10 = p10; c11 = p11;
    }
}

extern "C" void kernel_launch(void* const* d_in, const int* in_sizes, int n_in,
                              void* d_out, int out_size)
{
    const float*  x    = (const float*)d_in[0];
    const float4* W1   = (const float4*)d_in[1];
    const float*  b1   = (const float*)d_in[2];
    const float*  W2   = (const float*)d_in[3];
    const float*  b2   = (const float*)d_in[4];
    const float*  W_Ld = (const float*)d_in[5];
    const float*  b_Ld = (const float*)d_in[6];
    const float*  W_Lo = (const float*)d_in[7];
    const float*  b_Lo = (const float*)d_in[8];
    float4* out = (float4*)d_out;

    const int n = in_sizes[0] / 4;                  // rows
    const int nwt = (n + 31) / 32;                  // 32-row warp-tiles
    int grid = (nwt + 3) / 4;
    if (grid > GRIDN) grid = GRIDN;
    dln_mma_kernel<<<grid, TPB>>>(x, W1, b1, W2, b2, W_Ld, b_Ld, W_Lo, b_Lo,
                                  out, n, nwt);
}

// round 15
// speedup vs baseline: 1.5972x; 1.5621x over previous
#include <cuda_runtime.h>
#include <cuda_fp16.h>

typedef unsigned long long u64;
typedef unsigned int u32;

// ---------- helpers ----------
__device__ __forceinline__ u64 pk(float a, float b) {
    u64 r; asm("mov.b64 %0, {%1,%2};" : "=l"(r) : "f"(a), "f"(b)); return r;
}
__device__ __forceinline__ u64 fma2(u64 a, u64 b, u64 c) {
    u64 d; asm("fma.rn.f32x2 %0, %1, %2, %3;" : "=l"(d) : "l"(a), "l"(b), "l"(c)); return d;
}
__device__ __forceinline__ float2 upk(u64 a) {
    float x, y; asm("mov.b64 {%0,%1}, %2;" : "=f"(x), "=f"(y) : "l"(a));
    return make_float2(x, y);
}
__device__ __forceinline__ float lrelu(float x) { return fmaxf(x, 0.01f * x); }
__device__ __forceinline__ float softplus_f(float x) {
    return fmaxf(x, 0.0f) + log1pf(expf(-fabsf(x)));
}
// pack two f32 -> f16x2: low half = first arg, high half = second arg
__device__ __forceinline__ u32 cvt_h2(float lo_val, float hi_val) {
    u32 r; asm("cvt.rn.f16x2.f32 %0, %1, %2;" : "=r"(r) : "f"(hi_val), "f"(lo_val));
    return r;
}
__device__ __forceinline__ float h2_lo(u32 v) {
    const __half2 h = *reinterpret_cast<const __half2*>(&v);
    return __low2float(h);
}
__device__ __forceinline__ float h2_hi(u32 v) {
    const __half2 h = *reinterpret_cast<const __half2*>(&v);
    return __high2float(h);
}

__device__ __forceinline__ void mma_k16(float* d, const u32* a, const u32* b) {
    asm volatile(
        "mma.sync.aligned.m16n8k16.row.col.f32.f16.f16.f32 "
        "{%0,%1,%2,%3}, {%4,%5,%6,%7}, {%8,%9}, {%0,%1,%2,%3};"
        : "+f"(d[0]), "+f"(d[1]), "+f"(d[2]), "+f"(d[3])
        : "r"(a[0]), "r"(a[1]), "r"(a[2]), "r"(a[3]), "r"(b[0]), "r"(b[1]));
}
__device__ __forceinline__ void mma_k8(float* d, u32 a0, u32 a1, u32 b0) {
    asm volatile(
        "mma.sync.aligned.m16n8k8.row.col.f32.f16.f16.f32 "
        "{%0,%1,%2,%3}, {%4,%5}, {%6}, {%0,%1,%2,%3};"
        : "+f"(d[0]), "+f"(d[1]), "+f"(d[2]), "+f"(d[3])
        : "r"(a0), "r"(a1), "r"(b0));
}

#define TPB 128
#define GRIDN 296   // 148 SMs * 2 CTAs

__global__ __launch_bounds__(TPB, 2)
void dln_mma_kernel(const float* __restrict__ xf,
                    const float4* __restrict__ W1, const float* __restrict__ b1,
                    const float* __restrict__ W2f, const float* __restrict__ b2,
                    const float* __restrict__ W_Ld, const float* __restrict__ b_Ld,
                    const float* __restrict__ W_Lo, const float* __restrict__ b_Lo,
                    float4* __restrict__ out, int n, int nwt)
{
    __shared__ u64   sBlo[8 * 4 * 32];   // W2-lo fragments [nt*4+kc][lane]
    __shared__ u64   sB2p[32];           // (b2[2i], b2[2i+1])
    __shared__ u64   sW3x[32];           // W_Ld row0 pairs
    __shared__ u64   sW3y[32];           // W_Ld row1 pairs
    __shared__ u64   sW3z[32];           // W_Lo pairs
    __shared__ float sB3[3];

    const int tid = threadIdx.x;
    const int wid = tid >> 5;
    const int lane = tid & 31;
    const int g = lane >> 2;     // row-in-8
    const int t = lane & 3;      // col-pair selector

    // ---- stage tables ----
    for (int i = tid; i < 32; i += TPB) {
        sB2p[i] = pk(b2[2 * i], b2[2 * i + 1]);
        sW3x[i] = pk(W_Ld[2 * i],      W_Ld[2 * i + 1]);
        sW3y[i] = pk(W_Ld[64 + 2 * i], W_Ld[64 + 2 * i + 1]);
        sW3z[i] = pk(W_Lo[2 * i],      W_Lo[2 * i + 1]);
    }
    if (tid == 0) { sB3[0] = b_Ld[0]; sB3[1] = b_Ld[1]; sB3[2] = b_Lo[0]; }

    // ---- W2 (layer-2 B): hi in regs, lo in SMEM (fp16 split) ----
    // frag (nt,kc): b0={B[k0][n],B[k0+1][n]}, b1={B[k0+8][n],B[k0+9][n]}, n=nt*8+g, k0=kc*16+2t
    u32 bhi[8][4][2];
#pragma unroll
    for (int nt = 0; nt < 8; nt++) {
#pragma unroll
        for (int kc = 0; kc < 4; kc++) {
            const int nn = nt * 8 + g;
            const int k0 = kc * 16 + 2 * t;
            const float f0 = W2f[nn * 64 + k0];
            const float f1 = W2f[nn * 64 + k0 + 1];
            const float f2 = W2f[nn * 64 + k0 + 8];
            const float f3 = W2f[nn * 64 + k0 + 9];
            const u32 h0 = cvt_h2(f0, f1);
            const u32 h1 = cvt_h2(f2, f3);
            bhi[nt][kc][0] = h0;
            bhi[nt][kc][1] = h1;
            if (wid == 0) {
                const u32 l0 = cvt_h2(f0 - h2_lo(h0), f1 - h2_hi(h0));
                const u32 l1 = cvt_h2(f2 - h2_lo(h1), f3 - h2_hi(h1));
                sBlo[(nt * 4 + kc) * 32 + lane] = ((u64)l1 << 32) | (u64)l0;
            }
        }
    }

    // ---- W1+bias (layer-1 B, K=5 padded into one k8 chunk): hi+lo in regs ----
    // k=0..3: W1 row; k=4: b1 (paired with x's constant-1 column); k>=5: zero
    u32 w1hi[8], w1lo[8];
#pragma unroll
    for (int nt = 0; nt < 8; nt++) {
        w1hi[nt] = 0u; w1lo[nt] = 0u;
        const int nn = nt * 8 + g;
        if (t < 2) {
            const float4 w = W1[nn];
            const float f0 = (t == 0) ? w.x : w.z;
            const float f1 = (t == 0) ? w.y : w.w;
            const u32 h = cvt_h2(f0, f1);
            w1hi[nt] = h;
            w1lo[nt] = cvt_h2(f0 - h2_lo(h), f1 - h2_hi(h));
        } else if (t == 2) {
            const float f0 = b1[nn];            // k=4 -> bias, k=5 -> 0
            const u32 h = cvt_h2(f0, 0.f);
            w1hi[nt] = h;
            w1lo[nt] = cvt_h2(f0 - h2_lo(h), 0.f);
        }
    }
    __syncthreads();

    const int TOTW = GRIDN * 4;
    int wt = blockIdx.x * 4 + wid;           // 32-row warp-tile index
    const float2* x2 = (const float2*)xf;

    // ---- prefetched x fragments for the CURRENT tile: [mt][row-half] ----
    float2 c00 = make_float2(0.f, 0.f), c01 = make_float2(0.f, 0.f);
    float2 c10 = make_float2(0.f, 0.f), c11 = make_float2(0.f, 0.f);
    if (wt < nwt && t < 2) {
        const int ra = wt * 32 + g;
        if (ra < n)      c00 = x2[ra * 2 + t];
        if (ra + 8 < n)  c01 = x2[(ra + 8) * 2 + t];
        if (ra + 16 < n) c10 = x2[(ra + 16) * 2 + t];
        if (ra + 24 < n) c11 = x2[(ra + 24) * 2 + t];
    }
    const float2 onec = (t == 2) ? make_float2(1.f, 0.f) : make_float2(0.f, 0.f);

    for (; wt < nwt; wt += TOTW) {
        // ---- issue next tile's x loads immediately ----
        const int nx = wt + TOTW;
        float2 p00 = make_float2(0.f, 0.f), p01 = make_float2(0.f, 0.f);
        float2 p10 = make_float2(0.f, 0.f), p11 = make_float2(0.f, 0.f);
        if (nx < nwt && t < 2) {
            const int ra = nx * 32 + g;
            if (ra < n)      p00 = x2[ra * 2 + t];
            if (ra + 8 < n)  p01 = x2[(ra + 8) * 2 + t];
            if (ra + 16 < n) p10 = x2[(ra + 16) * 2 + t];
            if (ra + 24 < n) p11 = x2[(ra + 24) * 2 + t];
        }

#pragma unroll
        for (int mt = 0; mt < 2; mt++) {
            const int r0 = wt * 32 + mt * 16 + g;
            const int r1 = r0 + 8;

            // ---- x fragments (k=4 real + constant-1 bias column at k=4..) ----
            const float2 vr0 = (mt == 0) ? c00 : c10;
            const float2 vr1 = (mt == 0) ? c01 : c11;
            const float2 v0 = (t == 2) ? onec : vr0;
            const float2 v1 = (t == 2) ? onec : vr1;
            const u32 a0h = cvt_h2(v0.x, v0.y);
            const u32 a1h = cvt_h2(v1.x, v1.y);

            // ---- layer-1 MMA: l1 = [x|1] @ [W1|b1]^T (2 passes, 8-wide ILP) ----
            float l1[8][4];
#pragma unroll
            for (int nt = 0; nt < 8; nt++) {
                l1[nt][0] = 0.f; l1[nt][1] = 0.f; l1[nt][2] = 0.f; l1[nt][3] = 0.f;
            }
#pragma unroll
            for (int nt = 0; nt < 8; nt++) mma_k8(l1[nt], a0h, a1h, w1hi[nt]);
#pragma unroll
            for (int nt = 0; nt < 8; nt++) mma_k8(l1[nt], a0h, a1h, w1lo[nt]);

            // ---- lrelu + fp16 split -> layer-2 A fragments (hi only) ----
            u32 ah[8][2];
#pragma unroll
            for (int nt = 0; nt < 8; nt++) {
                const float h00 = lrelu(l1[nt][0]);
                const float h01 = lrelu(l1[nt][1]);
                const float h10 = lrelu(l1[nt][2]);
                const float h11 = lrelu(l1[nt][3]);
                ah[nt][0] = cvt_h2(h00, h01);
                ah[nt][1] = cvt_h2(h10, h11);
            }

            // ---- layer-2 MMA: acc = h1 @ W2^T (2 passes, K=64) ----
            float acc[8][4];
#pragma unroll
            for (int nt = 0; nt < 8; nt++) {
                acc[nt][0] = 0.f; acc[nt][1] = 0.f; acc[nt][2] = 0.f; acc[nt][3] = 0.f;
            }
#pragma unroll
            for (int kc = 0; kc < 4; kc++) {
                u32 ahi4[4] = { ah[2 * kc][0], ah[2 * kc][1], ah[2 * kc + 1][0], ah[2 * kc + 1][1] };
                u32 bl[8][2];
#pragma unroll
                for (int nt = 0; nt < 8; nt++) {
                    const u64 v = sBlo[(nt * 4 + kc) * 32 + lane];
                    bl[nt][0] = (u32)v; bl[nt][1] = (u32)(v >> 32);
                }
#pragma unroll
                for (int nt = 0; nt < 8; nt++) mma_k16(acc[nt], ahi4, bhi[nt][kc]);
#pragma unroll
                for (int nt = 0; nt < 8; nt++) mma_k16(acc[nt], ahi4, bl[nt]);
            }

            // ---- epilogue: bias + lrelu + head + reduce + softplus + H ----
            u64 D0a = 0ULL, D1a = 0ULL, Oa = 0ULL;
            u64 D0b = 0ULL, D1b = 0ULL, Ob = 0ULL;
#pragma unroll
            for (int nt = 0; nt < 8; nt++) {
                const int i = nt * 4 + t;
                const float2 bb = upk(sB2p[i]);
                const u64 ha = pk(lrelu(acc[nt][0] + bb.x), lrelu(acc[nt][1] + bb.y));
                const u64 hb = pk(lrelu(acc[nt][2] + bb.x), lrelu(acc[nt][3] + bb.y));
                const u64 wx = sW3x[i], wy = sW3y[i], wz = sW3z[i];
                D0a = fma2(wx, ha, D0a); D1a = fma2(wy, ha, D1a); Oa = fma2(wz, ha, Oa);
                D0b = fma2(wx, hb, D0b); D1b = fma2(wy, hb, D1b); Ob = fma2(wz, hb, Ob);
            }
            float v0r, v1r, v2r, v3r, v4r, v5r;
            { const float2 e = upk(D0a); v0r = e.x + e.y; }
            { const float2 e = upk(D1a); v1r = e.x + e.y; }
            { const float2 e = upk(Oa);  v2r = e.x + e.y; }
            { const float2 e = upk(D0b); v3r = e.x + e.y; }
            { const float2 e = upk(D1b); v4r = e.x + e.y; }
            { const float2 e = upk(Ob);  v5r = e.x + e.y; }
            v0r += __shfl_xor_sync(0xffffffffu, v0r, 1); v0r += __shfl_xor_sync(0xffffffffu, v0r, 2);
            v1r += __shfl_xor_sync(0xffffffffu, v1r, 1); v1r += __shfl_xor_sync(0xffffffffu, v1r, 2);
            v2r += __shfl_xor_sync(0xffffffffu, v2r, 1); v2r += __shfl_xor_sync(0xffffffffu, v2r, 2);
            v3r += __shfl_xor_sync(0xffffffffu, v3r, 1); v3r += __shfl_xor_sync(0xffffffffu, v3r, 2);
            v4r += __shfl_xor_sync(0xffffffffu, v4r, 1); v4r += __shfl_xor_sync(0xffffffffu, v4r, 2);
            v5r += __shfl_xor_sync(0xffffffffu, v5r, 1); v5r += __shfl_xor_sync(0xffffffffu, v5r, 2);

            if (t == 0) {
                if (r0 < n) {
                    const float d0 = softplus_f(v0r + sB3[0]);
                    const float d1 = softplus_f(v1r + sB3[1]);
                    const float lo = v2r + sB3[2];
                    const float od = d0 * lo;
                    out[r0] = make_float4(fmaf(d0, d0, 1e-9f), od, od,
                                          fmaf(lo, lo, fmaf(d1, d1, 1e-9f)));
                }
                if (r1 < n) {
                    const float d0 = softplus_f(v3r + sB3[0]);
                    const float d1 = softplus_f(v4r + sB3[1]);
                    const float lo = v5r + sB3[2];
                    const float od = d0 * lo;
                    out[r1] = make_float4(fmaf(d0, d0, 1e-9f), od, od,
                                          fmaf(lo, lo, fmaf(d1, d1, 1e-9f)));
                }
            }
        }

        // rotate prefetched x into current slot
        c00 = p00; c01 = p01; c10 = p10; c11 = p11;
    }
}

extern "C" void kernel_launch(void* const* d_in, const int* in_sizes, int n_in,
                              void* d_out, int out_size)
{
    const float*  x    = (const float*)d_in[0];
    const float4* W1   = (const float4*)d_in[1];
    const float*  b1   = (const float*)d_in[2];
    const float*  W2   = (const float*)d_in[3];
    const float*  b2   = (const float*)d_in[4];
    const float*  W_Ld = (const float*)d_in[5];
    const float*  b_Ld = (const float*)d_in[6];
    const float*  W_Lo = (const float*)d_in[7];
    const float*  b_Lo = (const float*)d_in[8];
    float4* out = (float4*)d_out;

    const int n = in_sizes[0] / 4;                  // rows
    const int nwt = (n + 31) / 32;                  // 32-row warp-tiles
    int grid = (nwt + 3) / 4;
    if (grid > GRIDN) grid = GRIDN;
    dln_mma_kernel<<<grid, TPB>>>(x, W1, b1, W2, b2, W_Ld, b_Ld, W_Lo, b_Lo,
                                  out, n, nwt);
}

// round 16
// speedup vs baseline: 1.9578x; 1.2258x over previous
#include <cuda_runtime.h>
#include <cuda_fp16.h>

typedef unsigned long long u64;
typedef unsigned int u32;

// ---------- helpers ----------
__device__ __forceinline__ u64 pk(float a, float b) {
    u64 r; asm("mov.b64 %0, {%1,%2};" : "=l"(r) : "f"(a), "f"(b)); return r;
}
__device__ __forceinline__ u64 fma2(u64 a, u64 b, u64 c) {
    u64 d; asm("fma.rn.f32x2 %0, %1, %2, %3;" : "=l"(d) : "l"(a), "l"(b), "l"(c)); return d;
}
__device__ __forceinline__ float2 upk(u64 a) {
    float x, y; asm("mov.b64 {%0,%1}, %2;" : "=f"(x), "=f"(y) : "l"(a));
    return make_float2(x, y);
}
__device__ __forceinline__ float lrelu(float x) { return fmaxf(x, 0.01f * x); }
__device__ __forceinline__ float softplus_f(float x) {
    return fmaxf(x, 0.0f) + log1pf(expf(-fabsf(x)));
}
// pack two f32 -> f16x2: low half = first arg, high half = second arg
__device__ __forceinline__ u32 cvt_h2(float lo_val, float hi_val) {
    u32 r; asm("cvt.rn.f16x2.f32 %0, %1, %2;" : "=r"(r) : "f"(hi_val), "f"(lo_val));
    return r;
}

__device__ __forceinline__ void mma_k16(float* d, const u32* a, const u32* b) {
    asm volatile(
        "mma.sync.aligned.m16n8k16.row.col.f32.f16.f16.f32 "
        "{%0,%1,%2,%3}, {%4,%5,%6,%7}, {%8,%9}, {%0,%1,%2,%3};"
        : "+f"(d[0]), "+f"(d[1]), "+f"(d[2]), "+f"(d[3])
        : "r"(a[0]), "r"(a[1]), "r"(a[2]), "r"(a[3]), "r"(b[0]), "r"(b[1]));
}
__device__ __forceinline__ void mma_k8(float* d, u32 a0, u32 a1, u32 b0) {
    asm volatile(
        "mma.sync.aligned.m16n8k8.row.col.f32.f16.f16.f32 "
        "{%0,%1,%2,%3}, {%4,%5}, {%6}, {%0,%1,%2,%3};"
        : "+f"(d[0]), "+f"(d[1]), "+f"(d[2]), "+f"(d[3])
        : "r"(a0), "r"(a1), "r"(b0));
}

#define TPB 128
#define GRIDN 296   // 148 SMs * 2 CTAs

__global__ __launch_bounds__(TPB, 2)
void dln_mma_kernel(const float* __restrict__ xf,
                    const float4* __restrict__ W1, const float* __restrict__ b1,
                    const float* __restrict__ W2f, const float* __restrict__ b2,
                    const float* __restrict__ W_Ld, const float* __restrict__ b_Ld,
                    const float* __restrict__ W_Lo, const float* __restrict__ b_Lo,
                    float4* __restrict__ out, int n, int nwt)
{
    __shared__ u64   sB2p[32];           // (b2[2i], b2[2i+1])
    __shared__ u64   sW3x[32];           // W_Ld row0 pairs
    __shared__ u64   sW3y[32];           // W_Ld row1 pairs
    __shared__ u64   sW3z[32];           // W_Lo pairs
    __shared__ float sB3[3];

    const int tid = threadIdx.x;
    const int wid = tid >> 5;
    const int lane = tid & 31;
    const int g = lane >> 2;     // row-in-8
    const int t = lane & 3;      // col-pair selector

    // ---- stage tables ----
    for (int i = tid; i < 32; i += TPB) {
        sB2p[i] = pk(b2[2 * i], b2[2 * i + 1]);
        sW3x[i] = pk(W_Ld[2 * i],      W_Ld[2 * i + 1]);
        sW3y[i] = pk(W_Ld[64 + 2 * i], W_Ld[64 + 2 * i + 1]);
        sW3z[i] = pk(W_Lo[2 * i],      W_Lo[2 * i + 1]);
    }
    if (tid == 0) { sB3[0] = b_Ld[0]; sB3[1] = b_Ld[1]; sB3[2] = b_Lo[0]; }

    // ---- W2 (layer-2 B): fp16 hi fragments in regs ----
    // frag (nt,kc): b0={B[k0][n],B[k0+1][n]}, b1={B[k0+8][n],B[k0+9][n]}, n=nt*8+g, k0=kc*16+2t
    u32 bhi[8][4][2];
#pragma unroll
    for (int nt = 0; nt < 8; nt++) {
#pragma unroll
        for (int kc = 0; kc < 4; kc++) {
            const int nn = nt * 8 + g;
            const int k0 = kc * 16 + 2 * t;
            bhi[nt][kc][0] = cvt_h2(W2f[nn * 64 + k0],     W2f[nn * 64 + k0 + 1]);
            bhi[nt][kc][1] = cvt_h2(W2f[nn * 64 + k0 + 8], W2f[nn * 64 + k0 + 9]);
        }
    }

    // ---- W1+bias (layer-1 B, K=5 padded into one k8 chunk): fp16 in regs ----
    // k=0..3: W1 row; k=4: b1 (paired with x's constant-1 column); k>=5: zero
    u32 w1h[8];
#pragma unroll
    for (int nt = 0; nt < 8; nt++) {
        w1h[nt] = 0u;
        const int nn = nt * 8 + g;
        if (t < 2) {
            const float4 w = W1[nn];
            w1h[nt] = (t == 0) ? cvt_h2(w.x, w.y) : cvt_h2(w.z, w.w);
        } else if (t == 2) {
            w1h[nt] = cvt_h2(b1[nn], 0.f);
        }
    }
    __syncthreads();

    const int TOTW = GRIDN * 4;
    int wt = blockIdx.x * 4 + wid;           // 32-row warp-tile index
    const float2* x2 = (const float2*)xf;

    // ---- prefetched x fragments for the CURRENT tile: [mt][row-half] ----
    float2 c00 = make_float2(0.f, 0.f), c01 = make_float2(0.f, 0.f);
    float2 c10 = make_float2(0.f, 0.f), c11 = make_float2(0.f, 0.f);
    if (wt < nwt && t < 2) {
        const int ra = wt * 32 + g;
        if (ra < n)      c00 = x2[ra * 2 + t];
        if (ra + 8 < n)  c01 = x2[(ra + 8) * 2 + t];
        if (ra + 16 < n) c10 = x2[(ra + 16) * 2 + t];
        if (ra + 24 < n) c11 = x2[(ra + 24) * 2 + t];
    }
    const float2 onec = (t == 2) ? make_float2(1.f, 0.f) : make_float2(0.f, 0.f);

    for (; wt < nwt; wt += TOTW) {
        // ---- issue next tile's x loads immediately ----
        const int nx = wt + TOTW;
        float2 p00 = make_float2(0.f, 0.f), p01 = make_float2(0.f, 0.f);
        float2 p10 = make_float2(0.f, 0.f), p11 = make_float2(0.f, 0.f);
        if (nx < nwt && t < 2) {
            const int ra = nx * 32 + g;
            if (ra < n)      p00 = x2[ra * 2 + t];
            if (ra + 8 < n)  p01 = x2[(ra + 8) * 2 + t];
            if (ra + 16 < n) p10 = x2[(ra + 16) * 2 + t];
            if (ra + 24 < n) p11 = x2[(ra + 24) * 2 + t];
        }

#pragma unroll
        for (int mt = 0; mt < 2; mt++) {
            const int r0 = wt * 32 + mt * 16 + g;
            const int r1 = r0 + 8;

            // ---- x fragments (k=4 real + constant-1 bias column at k=4) ----
            const float2 vr0 = (mt == 0) ? c00 : c10;
            const float2 vr1 = (mt == 0) ? c01 : c11;
            const float2 v0 = (t == 2) ? onec : vr0;
            const float2 v1 = (t == 2) ? onec : vr1;
            const u32 a0h = cvt_h2(v0.x, v0.y);
            const u32 a1h = cvt_h2(v1.x, v1.y);

            // ---- layer-1 MMA: l1 = [x|1] @ [W1|b1]^T (single pass, 8-wide ILP) ----
            float l1[8][4];
#pragma unroll
            for (int nt = 0; nt < 8; nt++) {
                l1[nt][0] = 0.f; l1[nt][1] = 0.f; l1[nt][2] = 0.f; l1[nt][3] = 0.f;
            }
#pragma unroll
            for (int nt = 0; nt < 8; nt++) mma_k8(l1[nt], a0h, a1h, w1h[nt]);

            // ---- lrelu + fp16 -> layer-2 A fragments ----
            u32 ah[8][2];
#pragma unroll
            for (int nt = 0; nt < 8; nt++) {
                ah[nt][0] = cvt_h2(lrelu(l1[nt][0]), lrelu(l1[nt][1]));
                ah[nt][1] = cvt_h2(lrelu(l1[nt][2]), lrelu(l1[nt][3]));
            }

            // ---- layer-2 MMA: acc = h1 @ W2^T (single pass, K=64) ----
            float acc[8][4];
#pragma unroll
            for (int nt = 0; nt < 8; nt++) {
                acc[nt][0] = 0.f; acc[nt][1] = 0.f; acc[nt][2] = 0.f; acc[nt][3] = 0.f;
            }
#pragma unroll
            for (int kc = 0; kc < 4; kc++) {
                u32 ahi4[4] = { ah[2 * kc][0], ah[2 * kc][1], ah[2 * kc + 1][0], ah[2 * kc + 1][1] };
#pragma unroll
                for (int nt = 0; nt < 8; nt++) mma_k16(acc[nt], ahi4, bhi[nt][kc]);
            }

            // ---- epilogue: bias + lrelu + head + reduce + softplus + H ----
            u64 D0a = 0ULL, D1a = 0ULL, Oa = 0ULL;
            u64 D0b = 0ULL, D1b = 0ULL, Ob = 0ULL;
#pragma unroll
            for (int nt = 0; nt < 8; nt++) {
                const int i = nt * 4 + t;
                const float2 bb = upk(sB2p[i]);
                const u64 ha = pk(lrelu(acc[nt][0] + bb.x), lrelu(acc[nt][1] + bb.y));
                const u64 hb = pk(lrelu(acc[nt][2] + bb.x), lrelu(acc[nt][3] + bb.y));
                const u64 wx = sW3x[i], wy = sW3y[i], wz = sW3z[i];
                D0a = fma2(wx, ha, D0a); D1a = fma2(wy, ha, D1a); Oa = fma2(wz, ha, Oa);
                D0b = fma2(wx, hb, D0b); D1b = fma2(wy, hb, D1b); Ob = fma2(wz, hb, Ob);
            }
            float v0r, v1r, v2r, v3r, v4r, v5r;
            { const float2 e = upk(D0a); v0r = e.x + e.y; }
            { const float2 e = upk(D1a); v1r = e.x + e.y; }
            { const float2 e = upk(Oa);  v2r = e.x + e.y; }
            { const float2 e = upk(D0b); v3r = e.x + e.y; }
            { const float2 e = upk(D1b); v4r = e.x + e.y; }
            { const float2 e = upk(Ob);  v5r = e.x + e.y; }
            v0r += __shfl_xor_sync(0xffffffffu, v0r, 1); v0r += __shfl_xor_sync(0xffffffffu, v0r, 2);
            v1r += __shfl_xor_sync(0xffffffffu, v1r, 1); v1r += __shfl_xor_sync(0xffffffffu, v1r, 2);
            v2r += __shfl_xor_sync(0xffffffffu, v2r, 1); v2r += __shfl_xor_sync(0xffffffffu, v2r, 2);
            v3r += __shfl_xor_sync(0xffffffffu, v3r, 1); v3r += __shfl_xor_sync(0xffffffffu, v3r, 2);
            v4r += __shfl_xor_sync(0xffffffffu, v4r, 1); v4r += __shfl_xor_sync(0xffffffffu, v4r, 2);
            v5r += __shfl_xor_sync(0xffffffffu, v5r, 1); v5r += __shfl_xor_sync(0xffffffffu, v5r, 2);

            if (t == 0) {
                if (r0 < n) {
                    const float d0 = softplus_f(v0r + sB3[0]);
                    const float d1 = softplus_f(v1r + sB3[1]);
                    const float lo = v2r + sB3[2];
                    const float od = d0 * lo;
                    out[r0] = make_float4(fmaf(d0, d0, 1e-9f), od, od,
                                          fmaf(lo, lo, fmaf(d1, d1, 1e-9f)));
                }
                if (r1 < n) {
                    const float d0 = softplus_f(v3r + sB3[0]);
                    const float d1 = softplus_f(v4r + sB3[1]);
                    const float lo = v5r + sB3[2];
                    const float od = d0 * lo;
                    out[r1] = make_float4(fmaf(d0, d0, 1e-9f), od, od,
                                          fmaf(lo, lo, fmaf(d1, d1, 1e-9f)));
                }
            }
        }

        // rotate prefetched x into current slot
        c00 = p00; c01 = p01; c10 = p10; c11 = p11;
    }
}

extern "C" void kernel_launch(void* const* d_in, const int* in_sizes, int n_in,
                              void* d_out, int out_size)
{
    const float*  x    = (const float*)d_in[0];
    const float4* W1   = (const float4*)d_in[1];
    const float*  b1   = (const float*)d_in[2];
    const float*  W2   = (const float*)d_in[3];
    const float*  b2   = (const float*)d_in[4];
    const float*  W_Ld = (const float*)d_in[5];
    const float*  b_Ld = (const float*)d_in[6];
    const float*  W_Lo = (const float*)d_in[7];
    const float*  b_Lo = (const float*)d_in[8];
    float4* out = (float4*)d_out;

    const int n = in_sizes[0] / 4;                  // rows
    const int nwt = (n + 31) / 32;                  // 32-row warp-tiles
    int grid = (nwt + 3) / 4;
    if (grid > GRIDN) grid = GRIDN;
    dln_mma_kernel<<<grid, TPB>>>(x, W1, b1, W2, b2, W_Ld, b_Ld, W_Lo, b_Lo,
                                  out, n, nwt);
}

// round 17
// speedup vs baseline: 2.4761x; 1.2647x over previous
#include <cuda_runtime.h>
#include <cuda_fp16.h>

typedef unsigned long long u64;
typedef unsigned int u32;

// ---------- helpers ----------
__device__ __forceinline__ u64 pk(float a, float b) {
    u64 r; asm("mov.b64 %0, {%1,%2};" : "=l"(r) : "f"(a), "f"(b)); return r;
}
__device__ __forceinline__ float lrelu(float x) { return fmaxf(x, 0.01f * x); }
__device__ __forceinline__ float softplus_f(float x) {
    return fmaxf(x, 0.0f) + log1pf(expf(-fabsf(x)));
}
// pack two f32 -> f16x2: low half = first arg, high half = second arg
__device__ __forceinline__ u32 cvt_h2(float lo_val, float hi_val) {
    u32 r; asm("cvt.rn.f16x2.f32 %0, %1, %2;" : "=r"(r) : "f"(hi_val), "f"(lo_val));
    return r;
}
// half2 leaky-relu: max(v, 0.01*v)
__device__ __forceinline__ u32 lrelu2(u32 v) {
    __half2 h = *reinterpret_cast<__half2*>(&v);
    const __half2 s = __hmul2(h, __float2half2_rn(0.01f));
    h = __hmax2(h, s);
    return *reinterpret_cast<u32*>(&h);
}
__device__ __forceinline__ u32 hadd2u(u32 a, u32 b) {
    __half2 r = __hadd2(*reinterpret_cast<__half2*>(&a), *reinterpret_cast<__half2*>(&b));
    return *reinterpret_cast<u32*>(&r);
}

__device__ __forceinline__ void mma_k16(float* d, const u32* a, const u32* b) {
    asm volatile(
        "mma.sync.aligned.m16n8k16.row.col.f32.f16.f16.f32 "
        "{%0,%1,%2,%3}, {%4,%5,%6,%7}, {%8,%9}, {%0,%1,%2,%3};"
        : "+f"(d[0]), "+f"(d[1]), "+f"(d[2]), "+f"(d[3])
        : "r"(a[0]), "r"(a[1]), "r"(a[2]), "r"(a[3]), "r"(b[0]), "r"(b[1]));
}
__device__ __forceinline__ void mma_k8(float* d, u32 a0, u32 a1, u32 b0) {
    asm volatile(
        "mma.sync.aligned.m16n8k8.row.col.f32.f16.f16.f32 "
        "{%0,%1,%2,%3}, {%4,%5}, {%6}, {%0,%1,%2,%3};"
        : "+f"(d[0]), "+f"(d[1]), "+f"(d[2]), "+f"(d[3])
        : "r"(a0), "r"(a1), "r"(b0));
}

#define TPB 128
#define GRIDN 296   // 148 SMs * 2 CTAs

__global__ __launch_bounds__(TPB, 2)
void dln_mma_kernel(const float* __restrict__ xf,
                    const float4* __restrict__ W1, const float* __restrict__ b1,
                    const float* __restrict__ W2f, const float* __restrict__ b2,
                    const float* __restrict__ W_Ld, const float* __restrict__ b_Ld,
                    const float* __restrict__ W_Lo, const float* __restrict__ b_Lo,
                    float4* __restrict__ out, int n, int nwt)
{
    __shared__ u32   sB2h[32];           // half2 (b2[2i], b2[2i+1])
    __shared__ float sB3[3];

    const int tid = threadIdx.x;
    const int wid = tid >> 5;
    const int lane = tid & 31;
    const int g = lane >> 2;     // row-in-8
    const int t = lane & 3;      // col-pair selector

    // ---- stage tables ----
    for (int i = tid; i < 32; i += TPB)
        sB2h[i] = cvt_h2(b2[2 * i], b2[2 * i + 1]);
    if (tid == 0) { sB3[0] = b_Ld[0]; sB3[1] = b_Ld[1]; sB3[2] = b_Lo[0]; }

    // ---- W2 (layer-2 B): fp16 fragments in regs ----
    u32 bhi[8][4][2];
#pragma unroll
    for (int nt = 0; nt < 8; nt++) {
#pragma unroll
        for (int kc = 0; kc < 4; kc++) {
            const int nn = nt * 8 + g;
            const int k0 = kc * 16 + 2 * t;
            bhi[nt][kc][0] = cvt_h2(W2f[nn * 64 + k0],     W2f[nn * 64 + k0 + 1]);
            bhi[nt][kc][1] = cvt_h2(W2f[nn * 64 + k0 + 8], W2f[nn * 64 + k0 + 9]);
        }
    }

    // ---- W1+bias (layer-1 B, K=5 in one k8 chunk): fp16 in regs ----
    u32 w1h[8];
#pragma unroll
    for (int nt = 0; nt < 8; nt++) {
        w1h[nt] = 0u;
        const int nn = nt * 8 + g;
        if (t < 2) {
            const float4 w = W1[nn];
            w1h[nt] = (t == 0) ? cvt_h2(w.x, w.y) : cvt_h2(w.z, w.w);
        } else if (t == 2) {
            w1h[nt] = cvt_h2(b1[nn], 0.f);
        }
    }

    // ---- W3 (head B, n-tile of 8 with rows 0..2 real): fp16 in regs ----
    // B3[k][n] = W3[n][k]; n = g: 0 -> W_Ld row0, 1 -> W_Ld row1, 2 -> W_Lo, else 0
    u32 w3h[4][2];
    {
        const float* W3g = (g == 0) ? W_Ld : (g == 1) ? (W_Ld + 64) : (g == 2) ? W_Lo : 0;
#pragma unroll
        for (int kc = 0; kc < 4; kc++) {
            const int k0 = kc * 16 + 2 * t;
            if (W3g) {
                w3h[kc][0] = cvt_h2(W3g[k0],     W3g[k0 + 1]);
                w3h[kc][1] = cvt_h2(W3g[k0 + 8], W3g[k0 + 9]);
            } else {
                w3h[kc][0] = 0u; w3h[kc][1] = 0u;
            }
        }
    }
    __syncthreads();

    const int TOTW = GRIDN * 4;
    int wt = blockIdx.x * 4 + wid;           // 32-row warp-tile index
    const float2* x2 = (const float2*)xf;

    // ---- prefetched x fragments for the CURRENT tile ----
    float2 c00 = make_float2(0.f, 0.f), c01 = make_float2(0.f, 0.f);
    float2 c10 = make_float2(0.f, 0.f), c11 = make_float2(0.f, 0.f);
    if (wt < nwt && t < 2) {
        const int ra = wt * 32 + g;
        if (ra < n)      c00 = x2[ra * 2 + t];
        if (ra + 8 < n)  c01 = x2[(ra + 8) * 2 + t];
        if (ra + 16 < n) c10 = x2[(ra + 16) * 2 + t];
        if (ra + 24 < n) c11 = x2[(ra + 24) * 2 + t];
    }
    const float2 onec = (t == 2) ? make_float2(1.f, 0.f) : make_float2(0.f, 0.f);
    const float bLd0 = sB3[0], bLd1 = sB3[1], bLo = sB3[2];
    const int srcl = (lane & ~3) | 1;   // lane of t=1 in this quad-row

    for (; wt < nwt; wt += TOTW) {
        // ---- issue next tile's x loads immediately ----
        const int nx = wt + TOTW;
        float2 p00 = make_float2(0.f, 0.f), p01 = make_float2(0.f, 0.f);
        float2 p10 = make_float2(0.f, 0.f), p11 = make_float2(0.f, 0.f);
        if (nx < nwt && t < 2) {
            const int ra = nx * 32 + g;
            if (ra < n)      p00 = x2[ra * 2 + t];
            if (ra + 8 < n)  p01 = x2[(ra + 8) * 2 + t];
            if (ra + 16 < n) p10 = x2[(ra + 16) * 2 + t];
            if (ra + 24 < n) p11 = x2[(ra + 24) * 2 + t];
        }

#pragma unroll
        for (int mt = 0; mt < 2; mt++) {
            const int r0 = wt * 32 + mt * 16 + g;
            const int r1 = r0 + 8;

            // ---- x fragments (k=4 real + constant-1 bias column) ----
            const float2 vr0 = (mt == 0) ? c00 : c10;
            const float2 vr1 = (mt == 0) ? c01 : c11;
            const float2 v0 = (t == 2) ? onec : vr0;
            const float2 v1 = (t == 2) ? onec : vr1;
            const u32 a0h = cvt_h2(v0.x, v0.y);
            const u32 a1h = cvt_h2(v1.x, v1.y);

            // ---- layer-1 MMA: l1 = [x|1] @ [W1|b1]^T ----
            float l1[8][4];
#pragma unroll
            for (int nt = 0; nt < 8; nt++) {
                l1[nt][0] = 0.f; l1[nt][1] = 0.f; l1[nt][2] = 0.f; l1[nt][3] = 0.f;
            }
#pragma unroll
            for (int nt = 0; nt < 8; nt++) mma_k8(l1[nt], a0h, a1h, w1h[nt]);

            // ---- lrelu (fp16x2) -> layer-2 A fragments ----
            u32 ah[8][2];
#pragma unroll
            for (int nt = 0; nt < 8; nt++) {
                ah[nt][0] = lrelu2(cvt_h2(l1[nt][0], l1[nt][1]));
                ah[nt][1] = lrelu2(cvt_h2(l1[nt][2], l1[nt][3]));
            }

            // ---- layer-2 MMA: acc = h1 @ W2^T (K=64) ----
            float acc[8][4];
#pragma unroll
            for (int nt = 0; nt < 8; nt++) {
                acc[nt][0] = 0.f; acc[nt][1] = 0.f; acc[nt][2] = 0.f; acc[nt][3] = 0.f;
            }
#pragma unroll
            for (int kc = 0; kc < 4; kc++) {
                u32 ahi4[4] = { ah[2 * kc][0], ah[2 * kc][1], ah[2 * kc + 1][0], ah[2 * kc + 1][1] };
#pragma unroll
                for (int nt = 0; nt < 8; nt++) mma_k16(acc[nt], ahi4, bhi[nt][kc]);
            }

            // ---- bias + lrelu (fp16x2) -> h2 fragments for head MMA ----
            u32 h2[8][2];
#pragma unroll
            for (int nt = 0; nt < 8; nt++) {
                const u32 bb = sB2h[nt * 4 + t];
                h2[nt][0] = lrelu2(hadd2u(cvt_h2(acc[nt][0], acc[nt][1]), bb));
                h2[nt][1] = lrelu2(hadd2u(cvt_h2(acc[nt][2], acc[nt][3]), bb));
            }

            // ---- head MMA: [Ld0,Ld1,Lo] = h2 @ W3^T (4 MMAs) ----
            float hd[4] = {0.f, 0.f, 0.f, 0.f};
#pragma unroll
            for (int kc = 0; kc < 4; kc++) {
                u32 a4[4] = { h2[2 * kc][0], h2[2 * kc][1], h2[2 * kc + 1][0], h2[2 * kc + 1][1] };
                mma_k16(hd, a4, w3h[kc]);
            }
            // t=0 holds (Ld0,Ld1) rows g,g+8; t=1 holds (Lo, 0) rows g,g+8
            const float loA = __shfl_sync(0xffffffffu, hd[0], srcl);
            const float loB = __shfl_sync(0xffffffffu, hd[2], srcl);

            if (t == 0) {
                if (r0 < n) {
                    const float d0 = softplus_f(hd[0] + bLd0);
                    const float d1 = softplus_f(hd[1] + bLd1);
                    const float lo = loA + bLo;
                    const float od = d0 * lo;
                    out[r0] = make_float4(fmaf(d0, d0, 1e-9f), od, od,
                                          fmaf(lo, lo, fmaf(d1, d1, 1e-9f)));
                }
                if (r1 < n) {
                    const float d0 = softplus_f(hd[2] + bLd0);
                    const float d1 = softplus_f(hd[3] + bLd1);
                    const float lo = loB + bLo;
                    const float od = d0 * lo;
                    out[r1] = make_float4(fmaf(d0, d0, 1e-9f), od, od,
                                          fmaf(lo, lo, fmaf(d1, d1, 1e-9f)));
                }
            }
        }

        // rotate prefetched x into current slot
        c00 = p00; c01 = p01; c10 = p10; c11 = p11;
    }
}

extern "C" void kernel_launch(void* const* d_in, const int* in_sizes, int n_in,
                              void* d_out, int out_size)
{
    const float*  x    = (const float*)d_in[0];
    const float4* W1   = (const float4*)d_in[1];
    const float*  b1   = (const float*)d_in[2];
    const float*  W2   = (const float*)d_in[3];
    const float*  b2   = (const float*)d_in[4];
    const float*  W_Ld = (const float*)d_in[5];
    const float*  b_Ld = (const float*)d_in[6];
    const float*  W_Lo = (const float*)d_in[7];
    const float*  b_Lo = (const float*)d_in[8];
    float4* out = (float4*)d_out;

    const int n = in_sizes[0] / 4;                  // rows
    const int nwt = (n + 31) / 32;                  // 32-row warp-tiles
    int grid = (nwt + 3) / 4;
    if (grid > GRIDN) grid = GRIDN;
    dln_mma_kernel<<<grid, TPB>>>(x, W1, b1, W2, b2, W_Ld, b_Ld, W_Lo, b_Lo,
                                  out, n, nwt);
}